// round 4
// baseline (speedup 1.0000x reference)
#include <cuda_runtime.h>
#include <math.h>
#include <stdint.h>

// ---------------------------------------------------------------------------
// RetinaHead focal + smooth-L1 loss, decomposed pipeline:
//   1) rhl_assign : per-anchor IoU argmax; smooth-L1; appends pos/ignore
//                   anchors to a compact list (warp-aggregated atomics)
//   2) rhl_focal  : pure streaming "all-negative" focal sum over clas
//                   (6 instr/elt, DRAM-bound)
//   3) rhl_corr   : corrections for the rare ignore/positive anchors
//   4) rhl_final  : normalization + batch mean -> out[2]; resets state
// ---------------------------------------------------------------------------

#define MAX_B    64
#define MAX_LIST (16 * 1024 * 1024)
#define TILE     256

__device__ double   g_cls[MAX_B];    // zeroed at load; rhl_final re-zeros
__device__ double   g_reg[MAX_B];
__device__ int      g_npos[MAX_B];
__device__ int      g_cnt;
__device__ unsigned g_list[MAX_LIST];  // (globalAnchorIdx << 8) | (code+1)

// common focal pieces (must be used identically in focal + corr kernels)
__device__ __forceinline__ float clampc(float c) {
    return fminf(fmaxf(c, 1e-4f), 1.0f - 1e-4f);
}
// raw negative-case term BEFORE constant scale: c^2 * log2(1-c)   (<= 0)
__device__ __forceinline__ float fneg_raw(float c) {
    const float om = 1.0f - c;
    return __fmul_rn(c, c) * __log2f(om);
}
#define NEGK (0.75f * 0.6931471805599453f)   // 0.75*ln2 ; contribution = -NEGK * raw
#define POSK (0.25f * 0.6931471805599453f)

// ======================= kernel 1: assignment ==============================
__global__ __launch_bounds__(TILE)
void rhl_assign(const float* __restrict__ anchors,
                const float* __restrict__ targets,
                const float* __restrict__ regs,
                int A, int T)
{
    extern __shared__ char smem_raw[];
    float4* s_box  = (float4*)smem_raw;                                 // [T]
    float*  s_area = (float*)(smem_raw + sizeof(float4) * (size_t)T);   // [T]
    float*  s_lab  = s_area + T;                                        // [T]

    __shared__ float s_r[TILE / 32];
    __shared__ int   s_n[TILE / 32];

    const int tid = threadIdx.x;
    const int b   = blockIdx.y;
    const int a   = blockIdx.x * TILE + tid;

    for (int t = tid; t < T; t += TILE) {
        const float* tp = targets + ((size_t)b * T + t) * 5;
        float x1 = tp[0], y1 = tp[1], x2 = tp[2], y2 = tp[3];
        const float lb = tp[4];
        if (lb == -1.0f) { x1 = y1 = x2 = y2 = 0.0f; }   // degenerate -> iou == 0
        s_box[t]  = make_float4(x1, y1, x2, y2);
        s_area[t] = __fmul_rn(x2 - x1, y2 - y1);
        s_lab[t]  = lb;
    }
    __syncthreads();

    float regloss = 0.0f;
    int   npos    = 0;
    int   code    = -2;

    if (a < A) {
        const float4 ab = ((const float4*)anchors)[a];
        const float ax1 = ab.x, ay1 = ab.y, ax2 = ab.z, ay2 = ab.w;
        const float areaA = __fmul_rn(ax2 - ax1, ay2 - ay1);

        float best = 0.0f;          // all ious >= 0 (degenerate targets give 0)
        int   bestt = 0;
        #pragma unroll 4
        for (int t = 0; t < T; ++t) {
            const float4 tb = s_box[t];
            const float lx = fmaxf(ax1, tb.x), ly = fmaxf(ay1, tb.y);
            const float rx = fminf(ax2, tb.z), ry = fminf(ay2, tb.w);
            const float w = fmaxf(rx - lx, 0.0f), h = fmaxf(ry - ly, 0.0f);
            const float inter = __fmul_rn(w, h);
            // XLA op order: (area_a + area_b) - inter, IEEE divide
            const float iou = inter / ((areaA + s_area[t]) - inter);
            if (iou > best) { best = iou; bestt = t; }   // first-max argmax
        }

        if (best >= 0.5f) {
            code = (int)s_lab[bestt];
            npos = 1;
            const float4 tb = s_box[bestt];
            const float pcx = (ax1 + ax2) * 0.5f, pcy = (ay1 + ay2) * 0.5f;
            const float pw  = ax2 - ax1,          ph  = ay2 - ay1;
            const float g0 = ((tb.x + tb.z) * 0.5f - pcx) / (0.1f * pw);
            const float g1 = ((tb.y + tb.w) * 0.5f - pcy) / (0.1f * ph);
            const float g2 = logf((tb.z - tb.x) / pw) / 0.2f;
            const float g3 = logf((tb.w - tb.y) / ph) / 0.2f;
            const float4 rg = ((const float4*)regs)[(size_t)b * A + a];
            const float ge[4] = {g0, g1, g2, g3};
            const float rr[4] = {rg.x, rg.y, rg.z, rg.w};
            #pragma unroll
            for (int k = 0; k < 4; ++k) {
                const float d = fabsf(ge[k] - rr[k]);
                regloss += (d <= (1.0f/9.0f)) ? (4.5f * d) * d
                                              : d - (0.5f/9.0f);
            }
        } else if (best >= 0.4f) {
            code = -1;   // ignore
        }
    }

    // ---- warp-aggregated append of pos/ignore anchors ----
    const bool want = (a < A) && (code != -2);
    const unsigned mask = __ballot_sync(0xffffffffu, want);
    if (mask) {
        const int lane   = tid & 31;
        const int leader = __ffs(mask) - 1;
        int base = 0;
        if (lane == leader) base = atomicAdd(&g_cnt, __popc(mask));
        base = __shfl_sync(0xffffffffu, base, leader);
        if (want) {
            const int off = __popc(mask & ((1u << lane) - 1u));
            const int pos = base + off;
            if (pos < MAX_LIST)
                g_list[pos] = ((unsigned)((size_t)b * A + a) << 8) |
                              (unsigned)(code + 1);
        }
    }

    // ---- block reduce reg loss / npos ----
    float rs = regloss; int ns = npos;
    #pragma unroll
    for (int o = 16; o; o >>= 1) {
        rs += __shfl_down_sync(0xffffffffu, rs, o);
        ns += __shfl_down_sync(0xffffffffu, ns, o);
    }
    const int wid = tid >> 5, lane = tid & 31;
    if (lane == 0) { s_r[wid] = rs; s_n[wid] = ns; }
    __syncthreads();
    if (tid == 0) {
        float tr = 0.0f; int tn = 0;
        #pragma unroll
        for (int w = 0; w < TILE / 32; ++w) { tr += s_r[w]; tn += s_n[w]; }
        if (tr != 0.0f) atomicAdd(&g_reg[b], (double)tr);
        if (tn)         atomicAdd(&g_npos[b], tn);
    }
}

// ======================= kernel 2: streaming negative focal ================
__global__ __launch_bounds__(TILE)
void rhl_focal(const float* __restrict__ clas, int n4)   // n4 = A*C/4 per image
{
    const int b = blockIdx.y;
    const float4* __restrict__ cp4 = (const float4*)clas + (size_t)b * n4;

    const int stride = gridDim.x * TILE;
    int i = blockIdx.x * TILE + threadIdx.x;

    float s0 = 0.0f, s1 = 0.0f, s2 = 0.0f, s3 = 0.0f;
    for (; i + 3 * stride < n4; i += 4 * stride) {
        const float4 v0 = __ldcs(cp4 + i);
        const float4 v1 = __ldcs(cp4 + i + stride);
        const float4 v2 = __ldcs(cp4 + i + 2 * stride);
        const float4 v3 = __ldcs(cp4 + i + 3 * stride);
        s0 += fneg_raw(clampc(v0.x)) + fneg_raw(clampc(v0.y))
            + fneg_raw(clampc(v0.z)) + fneg_raw(clampc(v0.w));
        s1 += fneg_raw(clampc(v1.x)) + fneg_raw(clampc(v1.y))
            + fneg_raw(clampc(v1.z)) + fneg_raw(clampc(v1.w));
        s2 += fneg_raw(clampc(v2.x)) + fneg_raw(clampc(v2.y))
            + fneg_raw(clampc(v2.z)) + fneg_raw(clampc(v2.w));
        s3 += fneg_raw(clampc(v3.x)) + fneg_raw(clampc(v3.y))
            + fneg_raw(clampc(v3.z)) + fneg_raw(clampc(v3.w));
    }
    for (; i < n4; i += stride) {
        const float4 v = __ldcs(cp4 + i);
        s0 += fneg_raw(clampc(v.x)) + fneg_raw(clampc(v.y))
            + fneg_raw(clampc(v.z)) + fneg_raw(clampc(v.w));
    }
    float acc = -NEGK * ((s0 + s1) + (s2 + s3));   // constant applied once

    __shared__ float s_c[TILE / 32];
    #pragma unroll
    for (int o = 16; o; o >>= 1)
        acc += __shfl_down_sync(0xffffffffu, acc, o);
    const int wid = threadIdx.x >> 5, lane = threadIdx.x & 31;
    if (lane == 0) s_c[wid] = acc;
    __syncthreads();
    if (threadIdx.x == 0) {
        float t = 0.0f;
        #pragma unroll
        for (int w = 0; w < TILE / 32; ++w) t += s_c[w];
        atomicAdd(&g_cls[b], (double)t);
    }
}

// ======================= kernel 3: corrections =============================
__global__ __launch_bounds__(TILE)
void rhl_corr(const float* __restrict__ clas, int A, int C)
{
    const int n = g_cnt;
    const int Q = C >> 2;
    for (int idx = blockIdx.x * TILE + threadIdx.x; idx < n;
         idx += gridDim.x * TILE) {
        const unsigned e = g_list[idx];
        const int gidx = (int)(e >> 8);
        const int code = (int)(e & 0xFFu) - 1;      // -1 ignore, >=0 class
        const int b    = gidx / A;
        const float* row = clas + (size_t)gidx * C;
        float delta;
        if (code < 0) {
            // ignore anchor: remove its all-negative contribution
            float s = 0.0f;
            if ((C & 3) == 0) {
                const float4* r4 = (const float4*)row;
                for (int j = 0; j < Q; ++j) {
                    const float4 v = __ldg(r4 + j);
                    s += fneg_raw(clampc(v.x)) + fneg_raw(clampc(v.y))
                       + fneg_raw(clampc(v.z)) + fneg_raw(clampc(v.w));
                }
            } else {
                for (int j = 0; j < C; ++j) s += fneg_raw(clampc(__ldg(row + j)));
            }
            delta = NEGK * s;                        // == -(-NEGK*s)
        } else {
            // positive anchor: matched class uses the "one" branch instead
            const float c  = clampc(__ldg(row + code));
            const float om = 1.0f - c;
            const float fneg = -NEGK * fneg_raw(c);               // counted by main
            const float fpos = -POSK * (__fmul_rn(om, om) * __log2f(c));
            delta = fpos - fneg;
        }
        atomicAdd(&g_cls[b], (double)delta);
    }
}

// ======================= kernel 4: finalize + reset ========================
__global__ void rhl_final(const float* __restrict__ targets,
                          float* __restrict__ out, int B, int T)
{
    __shared__ double sh_c[8], sh_r[8];
    const int wid  = threadIdx.x >> 5;
    const int lane = threadIdx.x & 31;

    double cs = 0.0, rs = 0.0;
    for (int b = wid; b < B; b += 8) {
        bool v = false;
        for (int t = lane; t < T; t += 32)
            v |= (targets[((size_t)b * T + t) * 5 + 4] != -1.0f);
        const bool hv = __any_sync(0xffffffffu, v);
        if (lane == 0) {
            const int np = g_npos[b];
            const double npd = (double)np;
            cs += hv ? g_cls[b] / fmax(npd, 1.0) : 0.0;
            rs += (hv && np > 0) ? g_reg[b] / (npd * 4.0) : 0.0;
        }
    }
    if (lane == 0) { sh_c[wid] = cs; sh_r[wid] = rs; }
    __syncthreads();
    if (threadIdx.x == 0) {
        double tc = 0.0, tr = 0.0;
        for (int w = 0; w < 8; ++w) { tc += sh_c[w]; tr += sh_r[w]; }
        out[0] = (float)(tc / (double)B);
        out[1] = (float)(tr / (double)B);
    }
    __syncthreads();
    // reset accumulators for the next graph replay
    if (threadIdx.x < MAX_B) {
        g_cls[threadIdx.x] = 0.0;
        g_reg[threadIdx.x] = 0.0;
        g_npos[threadIdx.x] = 0;
    }
    if (threadIdx.x == 0) g_cnt = 0;
}

// ===========================================================================
extern "C" void kernel_launch(void* const* d_in, const int* in_sizes, int n_in,
                              void* d_out, int out_size)
{
    const float* clas    = (const float*)d_in[0];
    const float* regs    = (const float*)d_in[1];
    const float* anchors = (const float*)d_in[2];
    const float* targets = (const float*)d_in[3];
    float* out = (float*)d_out;

    const int A = in_sizes[2] / 4;                 // anchors [1,A,4]
    const int B = in_sizes[1] / (A * 4);           // regs [B,A,4]
    const int C = in_sizes[0] / (B * A);           // clas [B,A,C]
    const int T = in_sizes[3] / (B * 5);           // targets [B,T,5]

    // 1) assignment + list build
    {
        dim3 grid((A + TILE - 1) / TILE, B);
        const size_t smem = (sizeof(float4) + 2 * sizeof(float)) * (size_t)T;
        rhl_assign<<<grid, TILE, smem>>>(anchors, targets, regs, A, T);
    }
    // 2) streaming negative-focal reduction (C must be multiple of 4 here;
    //    C==80 for this problem). Fallback path handled inside corr otherwise.
    {
        dim3 grid(148, B);
        rhl_focal<<<grid, TILE>>>(clas, A * (C / 4));
    }
    // 3) corrections for pos/ignore anchors
    rhl_corr<<<64, TILE>>>(clas, A, C);
    // 4) finalize + reset
    rhl_final<<<1, 256>>>(targets, out, B, T);
}

// round 5
// speedup vs baseline: 1.1652x; 1.1652x over previous
#include <cuda_runtime.h>
#include <math.h>
#include <stdint.h>

// ---------------------------------------------------------------------------
// RetinaHead focal + smooth-L1 loss — single fused kernel.
//   clas [B,A,C] f32, regs [B,A,4] f32, anchors [1,A,4] f32,
//   targets [B,T,5] f32 (label -1 => padded)
// out: [2] f32 = (mean cls loss, mean reg loss)
//
// Per block (256-anchor tile of one image):
//   phase 1: IoU argmax -> pos/neg/ignore; smooth-L1; rare-anchor focal
//            corrections (own clas row only)
//   phase 2: all-negative focal stream over tile's clas (DRAM-bound)
//   reduce -> per-image double atomics; last block finalizes + resets.
// ---------------------------------------------------------------------------

#define MAX_B 64
#define TILE  256

__device__ double   g_cls[MAX_B];    // zero at load; last block re-zeros
__device__ double   g_reg[MAX_B];
__device__ int      g_npos[MAX_B];
__device__ unsigned g_done;

__device__ __forceinline__ float clampc(float c) {
    return fminf(fmaxf(c, 1e-4f), 1.0f - 1e-4f);
}
// raw negative term before scaling: c^2 * log2(1-c)  (<= 0)
__device__ __forceinline__ float fneg_raw(float c) {
    return __fmul_rn(c, c) * __log2f(1.0f - c);
}
#define NEGK (0.75f * 0.6931471805599453f)   // negative contribution = -NEGK*raw
#define POSK (0.25f * 0.6931471805599453f)

__global__ __launch_bounds__(TILE)
void rhl_fused(const float* __restrict__ clas,
               const float* __restrict__ regs,
               const float* __restrict__ anchors,
               const float* __restrict__ targets,
               float* __restrict__ out,
               int A, int C, int T, int B)
{
    extern __shared__ char smem_raw[];
    float4* s_box  = (float4*)smem_raw;                                 // [T]
    float*  s_area = (float*)(smem_raw + sizeof(float4) * (size_t)T);   // [T]

    __shared__ float s_cw[TILE / 32];
    __shared__ float s_rw[TILE / 32];
    __shared__ int   s_nw[TILE / 32];
    __shared__ bool  s_last;

    const int tid = threadIdx.x;
    const int b   = blockIdx.y;
    const int a0  = blockIdx.x * TILE;
    const int a   = a0 + tid;

    // ---- load & pack targets (degenerate box for padded -> IoU == 0) ----
    for (int t = tid; t < T; t += TILE) {
        const float* tp = targets + ((size_t)b * T + t) * 5;
        float x1 = tp[0], y1 = tp[1], x2 = tp[2], y2 = tp[3];
        if (tp[4] == -1.0f) { x1 = y1 = x2 = y2 = 0.0f; }
        s_box[t]  = make_float4(x1, y1, x2, y2);
        s_area[t] = __fmul_rn(x2 - x1, y2 - y1);
    }
    __syncthreads();

    // ================= phase 1: assignment + rare corrections ==============
    float cls_acc = 0.0f;   // accumulates corrections now, stream later
    float regloss = 0.0f;
    int   npos    = 0;

    if (a < A) {
        const float4 ab = ((const float4*)anchors)[a];
        const float ax1 = ab.x, ay1 = ab.y, ax2 = ab.z, ay2 = ab.w;
        const float areaA = __fmul_rn(ax2 - ax1, ay2 - ay1);

        float best = 0.0f;            // IoUs are >= 0 (degenerate give 0)
        int   bestt = 0;
        #pragma unroll 2
        for (int t = 0; t < T; ++t) {
            const float4 tb = s_box[t];
            const float lx = fmaxf(ax1, tb.x), ly = fmaxf(ay1, tb.y);
            const float rx = fminf(ax2, tb.z), ry = fminf(ay2, tb.w);
            const float w = fmaxf(rx - lx, 0.0f), h = fmaxf(ry - ly, 0.0f);
            const float inter = __fmul_rn(w, h);
            // XLA op order: (area_a + area_b) - inter, IEEE divide
            const float iou = inter / ((areaA + s_area[t]) - inter);
            if (iou > best) { best = iou; bestt = t; }   // first-max argmax
        }

        if (best >= 0.4f) {
            const float* row = clas + ((size_t)b * A + a) * C;
            if (best >= 0.5f) {
                // ---- positive: smooth-L1 + focal swap on matched class ----
                npos = 1;
                const int cls = (int)targets[((size_t)b * T + bestt) * 5 + 4];
                const float c  = clampc(__ldg(row + cls));
                const float om = 1.0f - c;
                const float fneg_c = -NEGK * fneg_raw(c);
                const float fpos_c = -POSK * (__fmul_rn(om, om) * __log2f(c));
                cls_acc += fpos_c - fneg_c;

                const float4 tb = s_box[bestt];
                const float pcx = (ax1 + ax2) * 0.5f, pcy = (ay1 + ay2) * 0.5f;
                const float pw  = ax2 - ax1,          ph  = ay2 - ay1;
                const float g0 = ((tb.x + tb.z) * 0.5f - pcx) / (0.1f * pw);
                const float g1 = ((tb.y + tb.w) * 0.5f - pcy) / (0.1f * ph);
                const float g2 = logf((tb.z - tb.x) / pw) / 0.2f;
                const float g3 = logf((tb.w - tb.y) / ph) / 0.2f;
                const float4 rg = ((const float4*)regs)[(size_t)b * A + a];
                const float ge[4] = {g0, g1, g2, g3};
                const float rr[4] = {rg.x, rg.y, rg.z, rg.w};
                #pragma unroll
                for (int k = 0; k < 4; ++k) {
                    const float d = fabsf(ge[k] - rr[k]);
                    regloss += (d <= (1.0f/9.0f)) ? (4.5f * d) * d
                                                  : d - (0.5f/9.0f);
                }
            } else {
                // ---- ignore: cancel this row's all-negative contribution ----
                float s = 0.0f;
                if ((C & 3) == 0) {
                    const float4* r4 = (const float4*)row;
                    const int Q = C >> 2;
                    #pragma unroll 4
                    for (int j = 0; j < Q; ++j) {
                        const float4 v = __ldg(r4 + j);
                        s += fneg_raw(clampc(v.x)) + fneg_raw(clampc(v.y))
                           + fneg_raw(clampc(v.z)) + fneg_raw(clampc(v.w));
                    }
                } else {
                    for (int j = 0; j < C; ++j) s += fneg_raw(clampc(__ldg(row + j)));
                }
                cls_acc += NEGK * s;       // == -(-NEGK*s)
            }
        }
    }

    // ================= phase 2: all-negative focal stream ==================
    const int tileA = min(TILE, A - a0);
    if ((C & 3) == 0) {
        const float4* __restrict__ cp4 =
            (const float4*)(clas + ((size_t)b * A + a0) * C);
        const int n4 = tileA * (C >> 2);
        int i = tid;
        float p0 = 0.0f, p1 = 0.0f, p2 = 0.0f, p3 = 0.0f;
        for (; i + 3 * TILE < n4; i += 4 * TILE) {
            const float4 v0 = __ldg(cp4 + i);
            const float4 v1 = __ldg(cp4 + i + TILE);
            const float4 v2 = __ldg(cp4 + i + 2 * TILE);
            const float4 v3 = __ldg(cp4 + i + 3 * TILE);
            p0 += fneg_raw(clampc(v0.x)) + fneg_raw(clampc(v0.y))
                + fneg_raw(clampc(v0.z)) + fneg_raw(clampc(v0.w));
            p1 += fneg_raw(clampc(v1.x)) + fneg_raw(clampc(v1.y))
                + fneg_raw(clampc(v1.z)) + fneg_raw(clampc(v1.w));
            p2 += fneg_raw(clampc(v2.x)) + fneg_raw(clampc(v2.y))
                + fneg_raw(clampc(v2.z)) + fneg_raw(clampc(v2.w));
            p3 += fneg_raw(clampc(v3.x)) + fneg_raw(clampc(v3.y))
                + fneg_raw(clampc(v3.z)) + fneg_raw(clampc(v3.w));
        }
        for (; i < n4; i += TILE) {
            const float4 v = __ldg(cp4 + i);
            p0 += fneg_raw(clampc(v.x)) + fneg_raw(clampc(v.y))
                + fneg_raw(clampc(v.z)) + fneg_raw(clampc(v.w));
        }
        cls_acc += -NEGK * ((p0 + p1) + (p2 + p3));
    } else {
        const float* cp = clas + ((size_t)b * A + a0) * C;
        const int n = tileA * C;
        float p = 0.0f;
        for (int i = tid; i < n; i += TILE) p += fneg_raw(clampc(__ldg(cp + i)));
        cls_acc += -NEGK * p;
    }

    // ================= block reduce + per-image atomics ====================
    float cs = cls_acc, rs = regloss;
    int   ns = npos;
    #pragma unroll
    for (int o = 16; o; o >>= 1) {
        cs += __shfl_down_sync(0xffffffffu, cs, o);
        rs += __shfl_down_sync(0xffffffffu, rs, o);
        ns += __shfl_down_sync(0xffffffffu, ns, o);
    }
    const int wid = tid >> 5, lane = tid & 31;
    if (lane == 0) { s_cw[wid] = cs; s_rw[wid] = rs; s_nw[wid] = ns; }
    __syncthreads();
    if (tid == 0) {
        float tc = 0.0f, tr = 0.0f; int tn = 0;
        #pragma unroll
        for (int w = 0; w < TILE / 32; ++w) { tc += s_cw[w]; tr += s_rw[w]; tn += s_nw[w]; }
        atomicAdd(&g_cls[b], (double)tc);
        if (tr != 0.0f) atomicAdd(&g_reg[b], (double)tr);
        if (tn)         atomicAdd(&g_npos[b], tn);
        __threadfence();
        const unsigned total = gridDim.x * gridDim.y;
        s_last = (atomicAdd(&g_done, 1u) == total - 1u);
    }
    __syncthreads();

    // ================= last block: finalize + reset ========================
    if (s_last) {
        __threadfence();
        __shared__ double f_c[MAX_B], f_r[MAX_B];
        if (tid < B) {
            bool hv = false;
            for (int t = 0; t < T; ++t)
                if (targets[((size_t)tid * T + t) * 5 + 4] != -1.0f) { hv = true; break; }
            const int np = g_npos[tid];
            const double npd = (double)np;
            f_c[tid] = hv ? g_cls[tid] / fmax(npd, 1.0) : 0.0;
            f_r[tid] = (hv && np > 0) ? g_reg[tid] / (npd * 4.0) : 0.0;
        }
        __syncthreads();
        if (tid == 0) {
            double tc = 0.0, tr = 0.0;
            for (int i = 0; i < B; ++i) { tc += f_c[i]; tr += f_r[i]; }
            out[0] = (float)(tc / (double)B);
            out[1] = (float)(tr / (double)B);
            g_done = 0u;
        }
        if (tid < MAX_B) { g_cls[tid] = 0.0; g_reg[tid] = 0.0; g_npos[tid] = 0; }
    }
}

// ===========================================================================
extern "C" void kernel_launch(void* const* d_in, const int* in_sizes, int n_in,
                              void* d_out, int out_size)
{
    const float* clas    = (const float*)d_in[0];
    const float* regs    = (const float*)d_in[1];
    const float* anchors = (const float*)d_in[2];
    const float* targets = (const float*)d_in[3];
    float* out = (float*)d_out;

    const int A = in_sizes[2] / 4;                 // anchors [1,A,4]
    const int B = in_sizes[1] / (A * 4);           // regs [B,A,4]
    const int C = in_sizes[0] / (B * A);           // clas [B,A,C]
    const int T = in_sizes[3] / (B * 5);           // targets [B,T,5]

    dim3 grid((A + TILE - 1) / TILE, B);
    const size_t smem = (sizeof(float4) + sizeof(float)) * (size_t)T;
    rhl_fused<<<grid, TILE, smem>>>(clas, regs, anchors, targets, out, A, C, T, B);
}